// round 1
// baseline (speedup 1.0000x reference)
#include <cuda_runtime.h>
#include <cuda_bf16.h>

#define F 4096
#define TLEN 2000
#define NB (TLEN / 4)

// final hidden state scratch (device global: no allocs allowed)
__device__ float g_h_final[F];

__device__ __forceinline__ float fast_tanh(float x) {
    float y;
    asm("tanh.approx.f32 %0, %1;" : "=f"(y) : "f"(x));
    return y;
}
__device__ __forceinline__ float fast_sig(float x) {
    // sigmoid(x) = 0.5*tanh(0.5*x) + 0.5
    return fmaf(fast_tanh(0.5f * x), 0.5f, 0.5f);
}

__global__ void __launch_bounds__(32, 1) grud_scan_kernel(
    const float* __restrict__ inp,
    const float* __restrict__ x_mean,
    const float* __restrict__ w_dg_x, const float* __restrict__ w_dg_h,
    const float* __restrict__ w_xz,  const float* __restrict__ w_hz,  const float* __restrict__ w_mz,
    const float* __restrict__ w_xr,  const float* __restrict__ w_hr,  const float* __restrict__ w_mr,
    const float* __restrict__ w_xh,  const float* __restrict__ w_hh,  const float* __restrict__ w_mh,
    const float* __restrict__ b_dg_x, const float* __restrict__ b_dg_h,
    const float* __restrict__ b_z,   const float* __restrict__ b_r,   const float* __restrict__ b_h)
{
    const int i = blockIdx.x * 32 + threadIdx.x;

    // per-feature scalars (diagonal weights)
    const float xm  = x_mean[i];
    const float wdx = w_dg_x[i], wdh = w_dg_h[i];
    const float wxz = w_xz[i], whz = w_hz[i], wmz = w_mz[i];
    const float wxr = w_xr[i], whr = w_hr[i], wmr = w_mr[i];
    const float wxh = w_xh[i], whh = w_hh[i], wmh = w_mh[i];
    const float bdx = b_dg_x[i], bdh = b_dg_h[i];
    const float bz  = b_z[i],   br  = b_r[i],   bh = b_h[i];

    // inp layout: [3, F, T]; each thread owns contiguous rows of T floats.
    // i*T floats = 8000B offset -> 16B aligned, so float4 loads are legal.
    const float4* __restrict__ X4 = reinterpret_cast<const float4*>(inp + (size_t)i * TLEN);
    const float4* __restrict__ M4 = reinterpret_cast<const float4*>(inp + (size_t)F * TLEN + (size_t)i * TLEN);
    const float4* __restrict__ D4 = reinterpret_cast<const float4*>(inp + (size_t)2 * F * TLEN + (size_t)i * TLEN);

    float h = 0.0f;

    // one GRU-D step; only hg -> gates -> h is on the serial chain
    auto step = [&](float x, float m, float d) {
        float gx = __expf(-fmaxf(fmaf(wdx, d, bdx), 0.0f));
        float gh = __expf(-fmaxf(fmaf(wdh, d, bdh), 0.0f));
        // decay-imputed input: gx*x + (1-gx)*xm = xm + gx*(x-xm)
        float xi = fmaf(gx, x - xm, xm);
        // mask blend: m*x + (1-m)*xi = xi + m*(x-xi)
        float xp = fmaf(m, x - xi, xi);
        float az = fmaf(wxz, xp, fmaf(wmz, m, bz));
        float ar = fmaf(wxr, xp, fmaf(wmr, m, br));
        float ah = fmaf(wxh, xp, fmaf(wmh, m, bh));

        float hg = gh * h;
        float z  = fast_sig(fmaf(whz, hg, az));
        float r  = fast_sig(fmaf(whr, hg, ar));
        float ht = fast_tanh(fmaf(whh, r * hg, ah));
        // (1-z)*hg + z*ht = hg + z*(ht - hg)
        h = fmaf(z, ht - hg, hg);
    };

    // distance-2 float4 software prefetch pipeline
    float4 x0 = X4[0], m0 = M4[0], d0 = D4[0];
    float4 x1 = X4[1], m1 = M4[1], d1 = D4[1];

    for (int tb = 0; tb < NB; ++tb) {
        float4 xc = x0, mc = m0, dc = d0;
        x0 = x1; m0 = m1; d0 = d1;
        int pf = tb + 2;
        if (pf < NB) { x1 = X4[pf]; m1 = M4[pf]; d1 = D4[pf]; }

        step(xc.x, mc.x, dc.x);
        step(xc.y, mc.y, dc.y);
        step(xc.z, mc.z, dc.z);
        step(xc.w, mc.w, dc.w);
    }

    g_h_final[i] = h;
}

// output head: y[o] = sum_k w_hy[o, k] * h[k] + b_y[o], O=2
__global__ void __launch_bounds__(256, 1) grud_head_kernel(
    const float* __restrict__ w_hy,
    const float* __restrict__ b_y,
    float* __restrict__ out)
{
    __shared__ float s0[8], s1[8];
    const int tid = threadIdx.x;

    float a0 = 0.0f, a1 = 0.0f;
    for (int k = tid; k < F; k += 256) {
        float h = g_h_final[k];
        a0 = fmaf(w_hy[k], h, a0);
        a1 = fmaf(w_hy[F + k], h, a1);
    }
    #pragma unroll
    for (int o = 16; o > 0; o >>= 1) {
        a0 += __shfl_down_sync(0xffffffffu, a0, o);
        a1 += __shfl_down_sync(0xffffffffu, a1, o);
    }
    if ((tid & 31) == 0) { s0[tid >> 5] = a0; s1[tid >> 5] = a1; }
    __syncthreads();
    if (tid < 32) {
        a0 = (tid < 8) ? s0[tid] : 0.0f;
        a1 = (tid < 8) ? s1[tid] : 0.0f;
        #pragma unroll
        for (int o = 4; o > 0; o >>= 1) {
            a0 += __shfl_down_sync(0xffffffffu, a0, o);
            a1 += __shfl_down_sync(0xffffffffu, a1, o);
        }
        if (tid == 0) {
            out[0] = a0 + b_y[0];
            out[1] = a1 + b_y[1];
        }
    }
}

extern "C" void kernel_launch(void* const* d_in, const int* in_sizes, int n_in,
                              void* d_out, int out_size)
{
    // input order (reference signature):
    // 0: inp [3,F,T]        1: x_mean
    // 2: w_dg_x  3: w_dg_h  4: w_xz  5: w_hz  6: w_mz
    // 7: w_xr    8: w_hr    9: w_mr 10: w_xh 11: w_hh 12: w_mh
    // 13: w_hy [2,F]
    // 14: b_dg_x 15: b_dg_h 16: b_z 17: b_r 18: b_h 19: b_y
    const float* inp    = (const float*)d_in[0];
    const float* x_mean = (const float*)d_in[1];
    const float* w_dg_x = (const float*)d_in[2];
    const float* w_dg_h = (const float*)d_in[3];
    const float* w_xz   = (const float*)d_in[4];
    const float* w_hz   = (const float*)d_in[5];
    const float* w_mz   = (const float*)d_in[6];
    const float* w_xr   = (const float*)d_in[7];
    const float* w_hr   = (const float*)d_in[8];
    const float* w_mr   = (const float*)d_in[9];
    const float* w_xh   = (const float*)d_in[10];
    const float* w_hh   = (const float*)d_in[11];
    const float* w_mh   = (const float*)d_in[12];
    const float* w_hy   = (const float*)d_in[13];
    const float* b_dg_x = (const float*)d_in[14];
    const float* b_dg_h = (const float*)d_in[15];
    const float* b_z    = (const float*)d_in[16];
    const float* b_r    = (const float*)d_in[17];
    const float* b_h    = (const float*)d_in[18];
    const float* b_y    = (const float*)d_in[19];
    float* out = (float*)d_out;

    grud_scan_kernel<<<F / 32, 32>>>(
        inp, x_mean, w_dg_x, w_dg_h,
        w_xz, w_hz, w_mz, w_xr, w_hr, w_mr, w_xh, w_hh, w_mh,
        b_dg_x, b_dg_h, b_z, b_r, b_h);

    grud_head_kernel<<<1, 256>>>(w_hy, b_y, out);
}

// round 2
// speedup vs baseline: 1.1002x; 1.1002x over previous
#include <cuda_runtime.h>
#include <cuda_bf16.h>

#define F 4096
#define TLEN 2000
#define NB (TLEN / 4)
#define NWARP (F / 32)

// partial dot products per scan warp (device global: no allocs allowed)
__device__ float g_part0[NWARP];
__device__ float g_part1[NWARP];

__device__ __forceinline__ float fast_tanh(float x) {
    float y;
    asm("tanh.approx.f32 %0, %1;" : "=f"(y) : "f"(x));
    return y;
}

__global__ void __launch_bounds__(32, 1) grud_scan_kernel(
    const float* __restrict__ inp,
    const float* __restrict__ x_mean,
    const float* __restrict__ w_dg_x, const float* __restrict__ w_dg_h,
    const float* __restrict__ w_xz,  const float* __restrict__ w_hz,  const float* __restrict__ w_mz,
    const float* __restrict__ w_xr,  const float* __restrict__ w_hr,  const float* __restrict__ w_mr,
    const float* __restrict__ w_xh,  const float* __restrict__ w_hh,  const float* __restrict__ w_mh,
    const float* __restrict__ b_dg_x, const float* __restrict__ b_dg_h,
    const float* __restrict__ b_z,   const float* __restrict__ b_r,   const float* __restrict__ b_h,
    const float* __restrict__ w_hy)
{
    const int i = blockIdx.x * 32 + threadIdx.x;

    // per-feature scalars; fold the sigmoid 0.5-scale into z/r coefficients,
    // and 0.5 into the h-tilde recurrent weight (for the r-affine fold).
    const float xm  = x_mean[i];
    const float wdx = w_dg_x[i], wdh = w_dg_h[i];
    const float bdx = b_dg_x[i], bdh = b_dg_h[i];

    const float cz_h = 0.5f * w_hz[i];
    const float cz_x = 0.5f * w_xz[i];
    const float cz_m = 0.5f * w_mz[i];
    const float cz_b = 0.5f * b_z[i];

    const float cr_h = 0.5f * w_hr[i];
    const float cr_x = 0.5f * w_xr[i];
    const float cr_m = 0.5f * w_mr[i];
    const float cr_b = 0.5f * b_r[i];

    const float ch_h = 0.5f * w_hh[i];   // folds r = 0.5*s_r + 0.5
    const float ch_x = w_xh[i];
    const float ch_m = w_mh[i];
    const float ch_b = b_h[i];

    // inp layout: [3, F, T]; each thread owns contiguous rows of T floats.
    const float4* __restrict__ X4 = reinterpret_cast<const float4*>(inp + (size_t)i * TLEN);
    const float4* __restrict__ M4 = reinterpret_cast<const float4*>(inp + (size_t)F * TLEN + (size_t)i * TLEN);
    const float4* __restrict__ D4 = reinterpret_cast<const float4*>(inp + (size_t)2 * F * TLEN + (size_t)i * TLEN);

    float h = 0.0f;

    // ---- one step, split into an input-only phase and a minimal serial phase
    struct Pre { float gh, Az, Ar, Ph, az, ar, ah; };

    auto precompute = [&](float x, float m, float d) -> Pre {
        Pre p;
        float tx = fmaf(wdx, d, bdx);
        float th = fmaf(wdh, d, bdh);
        float gx = __expf(-fmaxf(tx, 0.0f));
        p.gh     = __expf(-fmaxf(th, 0.0f));
        // decay-imputed + mask-blended input
        float xi = fmaf(gx, x - xm, xm);
        float xp = fmaf(m, x - xi, xi);
        // gate biases (input-dependent parts), z/r pre-scaled by 0.5
        p.az = fmaf(cz_x, xp, fmaf(cz_m, m, cz_b));
        p.ar = fmaf(cr_x, xp, fmaf(cr_m, m, cr_b));
        p.ah = fmaf(ch_x, xp, fmaf(ch_m, m, ch_b));
        // recurrent coefficients with gh folded in (off the serial chain)
        p.Az = cz_h * p.gh;
        p.Ar = cr_h * p.gh;
        p.Ph = ch_h * p.gh;
        return p;
    };

    // serial chain: fma -> tanh -> fma -> tanh -> sub -> fma  (~48 cyc)
    auto update = [&](const Pre& p) {
        float hg = p.gh * h;                       // parallel
        float q  = p.Ph * h;                       // parallel
        float qa = q + p.ah;                       // parallel
        float sz = fast_tanh(fmaf(p.Az, h, p.az)); // parallel to r-chain
        float sr = fast_tanh(fmaf(p.Ar, h, p.ar)); // chain
        float z  = fmaf(sz, 0.5f, 0.5f);           // ready before ht
        float ht = fast_tanh(fmaf(q, sr, qa));     // chain
        h = fmaf(z, ht - hg, hg);                  // chain
    };

    // distance-2 float4 software prefetch pipeline
    float4 x0 = X4[0], m0 = M4[0], d0 = D4[0];
    float4 x1 = X4[1], m1 = M4[1], d1 = D4[1];

    for (int tb = 0; tb < NB; ++tb) {
        float4 xc = x0, mc = m0, dc = d0;
        x0 = x1; m0 = m1; d0 = d1;
        int pf = tb + 2;
        if (pf < NB) { x1 = X4[pf]; m1 = M4[pf]; d1 = D4[pf]; }

        // input-only work for all 4 steps first: fills the chain's stall slots
        Pre p0 = precompute(xc.x, mc.x, dc.x);
        Pre p1 = precompute(xc.y, mc.y, dc.y);
        Pre p2 = precompute(xc.z, mc.z, dc.z);
        Pre p3 = precompute(xc.w, mc.w, dc.w);

        update(p0);
        update(p1);
        update(p2);
        update(p3);
    }

    // fused output-head partials: y[o] += w_hy[o,i] * h_i, warp-reduced
    float a0 = w_hy[i] * h;
    float a1 = w_hy[F + i] * h;
    #pragma unroll
    for (int o = 16; o > 0; o >>= 1) {
        a0 += __shfl_down_sync(0xffffffffu, a0, o);
        a1 += __shfl_down_sync(0xffffffffu, a1, o);
    }
    if (threadIdx.x == 0) {
        g_part0[blockIdx.x] = a0;
        g_part1[blockIdx.x] = a1;
    }
}

// tiny head: reduce 128 partials per output
__global__ void __launch_bounds__(128, 1) grud_head_kernel(
    const float* __restrict__ b_y,
    float* __restrict__ out)
{
    __shared__ float s0[4], s1[4];
    const int tid = threadIdx.x;
    float a0 = g_part0[tid];
    float a1 = g_part1[tid];
    #pragma unroll
    for (int o = 16; o > 0; o >>= 1) {
        a0 += __shfl_down_sync(0xffffffffu, a0, o);
        a1 += __shfl_down_sync(0xffffffffu, a1, o);
    }
    if ((tid & 31) == 0) { s0[tid >> 5] = a0; s1[tid >> 5] = a1; }
    __syncthreads();
    if (tid == 0) {
        out[0] = s0[0] + s0[1] + s0[2] + s0[3] + b_y[0];
        out[1] = s1[0] + s1[1] + s1[2] + s1[3] + b_y[1];
    }
}

extern "C" void kernel_launch(void* const* d_in, const int* in_sizes, int n_in,
                              void* d_out, int out_size)
{
    const float* inp    = (const float*)d_in[0];
    const float* x_mean = (const float*)d_in[1];
    const float* w_dg_x = (const float*)d_in[2];
    const float* w_dg_h = (const float*)d_in[3];
    const float* w_xz   = (const float*)d_in[4];
    const float* w_hz   = (const float*)d_in[5];
    const float* w_mz   = (const float*)d_in[6];
    const float* w_xr   = (const float*)d_in[7];
    const float* w_hr   = (const float*)d_in[8];
    const float* w_mr   = (const float*)d_in[9];
    const float* w_xh   = (const float*)d_in[10];
    const float* w_hh   = (const float*)d_in[11];
    const float* w_mh   = (const float*)d_in[12];
    const float* w_hy   = (const float*)d_in[13];
    const float* b_dg_x = (const float*)d_in[14];
    const float* b_dg_h = (const float*)d_in[15];
    const float* b_z    = (const float*)d_in[16];
    const float* b_r    = (const float*)d_in[17];
    const float* b_h    = (const float*)d_in[18];
    const float* b_y    = (const float*)d_in[19];
    float* out = (float*)d_out;

    grud_scan_kernel<<<NWARP, 32>>>(
        inp, x_mean, w_dg_x, w_dg_h,
        w_xz, w_hz, w_mz, w_xr, w_hr, w_mr, w_xh, w_hh, w_mh,
        b_dg_x, b_dg_h, b_z, b_r, b_h, w_hy);

    grud_head_kernel<<<1, 128>>>(b_y, out);
}

// round 3
// speedup vs baseline: 1.7389x; 1.5805x over previous
#include <cuda_runtime.h>
#include <cuda_bf16.h>

#define F 4096
#define TLEN 2000
#define NWARP (F / 32)        // 128 CTAs, one consumer warp each
#define CSTEPS 40             // steps per chunk
#define G4 (CSTEPS / 4)       // float4 groups per chunk = 10
#define CHUNKS (TLEN / CSTEPS) // 50

// cross-CTA reduction scratch
__device__ float g_part0[NWARP];
__device__ float g_part1[NWARP];
__device__ unsigned g_count = 0;

__device__ __forceinline__ float fast_tanh(float x) {
    float y;
    asm("tanh.approx.f32 %0, %1;" : "=f"(y) : "f"(x));
    return y;
}

#define BAR_SYNC(id)   asm volatile("bar.sync %0, 128;"   :: "r"(id) : "memory")
#define BAR_ARRIVE(id) asm volatile("bar.arrive %0, 128;" :: "r"(id) : "memory")
// barrier ids: FULL buffer b -> 1+b ; EMPTY buffer b -> 3+b

__global__ void __launch_bounds__(128, 1) grud_scan_kernel(
    const float* __restrict__ inp,
    const float* __restrict__ x_mean,
    const float* __restrict__ w_dg_x, const float* __restrict__ w_dg_h,
    const float* __restrict__ w_xz,  const float* __restrict__ w_hz,  const float* __restrict__ w_mz,
    const float* __restrict__ w_xr,  const float* __restrict__ w_hr,  const float* __restrict__ w_mr,
    const float* __restrict__ w_xh,  const float* __restrict__ w_hh,  const float* __restrict__ w_mh,
    const float* __restrict__ b_dg_x, const float* __restrict__ b_dg_h,
    const float* __restrict__ b_z,   const float* __restrict__ b_r,   const float* __restrict__ b_h,
    const float* __restrict__ w_hy,  const float* __restrict__ b_y,
    float* __restrict__ out)
{
    // sbuf[b][t][feat] = {gh, az, ar, ah}
    __shared__ float4 sbuf[2][CSTEPS][32];   // 40 KB

    const int lane = threadIdx.x & 31;
    const int wid  = threadIdx.x >> 5;       // 0 = consumer, 1..3 = producers
    const int i    = blockIdx.x * 32 + lane; // feature index

    if (wid != 0) {
        // ------------------ PRODUCER ------------------
        const float xm  = x_mean[i];
        const float wdx = w_dg_x[i], wdh = w_dg_h[i];
        const float bdx = b_dg_x[i], bdh = b_dg_h[i];
        const float cz_x = 0.5f * w_xz[i], cz_m = 0.5f * w_mz[i], cz_b = 0.5f * b_z[i];
        const float cr_x = 0.5f * w_xr[i], cr_m = 0.5f * w_mr[i], cr_b = 0.5f * b_r[i];
        const float ch_x = w_xh[i],        ch_m = w_mh[i],        ch_b = b_h[i];

        const float4* __restrict__ X4 = reinterpret_cast<const float4*>(inp + (size_t)i * TLEN);
        const float4* __restrict__ M4 = reinterpret_cast<const float4*>(inp + (size_t)F * TLEN + (size_t)i * TLEN);
        const float4* __restrict__ D4 = reinterpret_cast<const float4*>(inp + (size_t)2 * F * TLEN + (size_t)i * TLEN);

        const int w = wid - 1; // 0..2

        for (int c = 0; c < CHUNKS; ++c) {
            const int b = c & 1;
            if (c >= 2) BAR_SYNC(3 + b);              // wait: consumer freed buffer b

            // this producer handles float4 groups g = w, w+3, w+6, ...
            for (int g = w; g < G4; g += 3) {
                const int f4idx = c * G4 + g;
                float4 xv = X4[f4idx];
                float4 mv = M4[f4idx];
                float4 dv = D4[f4idx];

                const float xs[4] = {xv.x, xv.y, xv.z, xv.w};
                const float ms[4] = {mv.x, mv.y, mv.z, mv.w};
                const float ds[4] = {dv.x, dv.y, dv.z, dv.w};

                #pragma unroll
                for (int k = 0; k < 4; ++k) {
                    float x = xs[k], m = ms[k], d = ds[k];
                    float gx = __expf(-fmaxf(fmaf(wdx, d, bdx), 0.0f));
                    float gh = __expf(-fmaxf(fmaf(wdh, d, bdh), 0.0f));
                    float xi = fmaf(gx, x - xm, xm);       // decay-imputed
                    float xp = fmaf(m, x - xi, xi);        // mask blend
                    float az = fmaf(cz_x, xp, fmaf(cz_m, m, cz_b));
                    float ar = fmaf(cr_x, xp, fmaf(cr_m, m, cr_b));
                    float ah = fmaf(ch_x, xp, fmaf(ch_m, m, ch_b));
                    sbuf[b][g * 4 + k][lane] = make_float4(gh, az, ar, ah);
                }
            }
            asm volatile("membar.cta;" ::: "memory");     // STS visible before arrive
            BAR_ARRIVE(1 + b);                            // signal: buffer b full
        }
        return;
    }

    // ------------------ CONSUMER (warp 0) ------------------
    const float cz_h = 0.5f * w_hz[i];
    const float cr_h = 0.5f * w_hr[i];
    const float ch_h = 0.5f * w_hh[i];   // folds r = 0.5*s_r + 0.5

    float h = 0.0f;

    for (int c = 0; c < CHUNKS; ++c) {
        const int b = c & 1;
        BAR_SYNC(1 + b);                                  // wait: buffer b full

        float4 p = sbuf[b][0][lane];
        #pragma unroll 4
        for (int t = 0; t < CSTEPS; ++t) {
            float4 pn;
            if (t < CSTEPS - 1) pn = sbuf[b][t + 1][lane]; // prefetch (hidden by chain)

            const float gh = p.x, az = p.y, ar = p.z, ah = p.w;
            float Az = cz_h * gh;
            float Ar = cr_h * gh;
            float Ph = ch_h * gh;
            float hg = gh * h;
            float q  = Ph * h;
            float qa = q + ah;
            float sz = fast_tanh(fmaf(Az, h, az));        // off-chain
            float sr = fast_tanh(fmaf(Ar, h, ar));        // chain
            float z  = fmaf(sz, 0.5f, 0.5f);              // ready early
            float w0 = fmaf(-z, hg, hg);                  // (1-z)*hg, off-chain
            float ht = fast_tanh(fmaf(q, sr, qa));        // chain
            h = fmaf(z, ht, w0);                          // chain

            p = pn;
        }

        if (c < CHUNKS - 2) BAR_ARRIVE(3 + b);            // free buffer b
    }

    // fused output head: per-warp partial dot, then last-CTA-out final reduce
    float a0 = w_hy[i] * h;
    float a1 = w_hy[F + i] * h;
    #pragma unroll
    for (int o = 16; o > 0; o >>= 1) {
        a0 += __shfl_down_sync(0xffffffffu, a0, o);
        a1 += __shfl_down_sync(0xffffffffu, a1, o);
    }

    bool last = false;
    if (lane == 0) {
        g_part0[blockIdx.x] = a0;
        g_part1[blockIdx.x] = a1;
        __threadfence();
        unsigned old = atomicAdd(&g_count, 1u);
        last = (old == NWARP - 1);
    }
    last = __shfl_sync(0xffffffffu, last ? 1 : 0, 0) != 0;

    if (last) {
        __threadfence();
        float s0 = 0.0f, s1 = 0.0f;
        #pragma unroll
        for (int k = lane; k < NWARP; k += 32) {
            s0 += g_part0[k];
            s1 += g_part1[k];
        }
        #pragma unroll
        for (int o = 16; o > 0; o >>= 1) {
            s0 += __shfl_down_sync(0xffffffffu, s0, o);
            s1 += __shfl_down_sync(0xffffffffu, s1, o);
        }
        if (lane == 0) {
            out[0] = s0 + b_y[0];
            out[1] = s1 + b_y[1];
            g_count = 0;                                  // reset for next replay
        }
    }
}

extern "C" void kernel_launch(void* const* d_in, const int* in_sizes, int n_in,
                              void* d_out, int out_size)
{
    const float* inp    = (const float*)d_in[0];
    const float* x_mean = (const float*)d_in[1];
    const float* w_dg_x = (const float*)d_in[2];
    const float* w_dg_h = (const float*)d_in[3];
    const float* w_xz   = (const float*)d_in[4];
    const float* w_hz   = (const float*)d_in[5];
    const float* w_mz   = (const float*)d_in[6];
    const float* w_xr   = (const float*)d_in[7];
    const float* w_hr   = (const float*)d_in[8];
    const float* w_mr   = (const float*)d_in[9];
    const float* w_xh   = (const float*)d_in[10];
    const float* w_hh   = (const float*)d_in[11];
    const float* w_mh   = (const float*)d_in[12];
    const float* w_hy   = (const float*)d_in[13];
    const float* b_dg_x = (const float*)d_in[14];
    const float* b_dg_h = (const float*)d_in[15];
    const float* b_z    = (const float*)d_in[16];
    const float* b_r    = (const float*)d_in[17];
    const float* b_h    = (const float*)d_in[18];
    const float* b_y    = (const float*)d_in[19];
    float* out = (float*)d_out;

    grud_scan_kernel<<<NWARP, 128>>>(
        inp, x_mean, w_dg_x, w_dg_h,
        w_xz, w_hz, w_mz, w_xr, w_hr, w_mr, w_xh, w_hh, w_mh,
        b_dg_x, b_dg_h, b_z, b_r, b_h, w_hy, b_y, out);
}

// round 4
// speedup vs baseline: 2.7796x; 1.5985x over previous
#include <cuda_runtime.h>
#include <cuda_bf16.h>

#define F 4096
#define TLEN 2000
#define NWARP (F / 32)         // 128 CTAs, one consumer warp each
#define CSTEPS 40              // steps per chunk
#define G4 (CSTEPS / 4)        // float4 groups per chunk = 10
#define CHUNKS (TLEN / CSTEPS) // 50

// cross-CTA reduction scratch
__device__ float g_part0[NWARP];
__device__ float g_part1[NWARP];
__device__ unsigned g_count = 0;

__device__ __forceinline__ float fast_tanh(float x) {
    float y;
    asm("tanh.approx.f32 %0, %1;" : "=f"(y) : "f"(x));
    return y;
}

#define BAR_SYNC(id)   asm volatile("bar.sync %0, 128;"   :: "r"(id) : "memory")
#define BAR_ARRIVE(id) asm volatile("bar.arrive %0, 128;" :: "r"(id) : "memory")
// barrier ids: FULL buffer b -> 1+b ; EMPTY buffer b -> 3+b

__global__ void __launch_bounds__(128, 1) grud_scan_kernel(
    const float* __restrict__ inp,
    const float* __restrict__ x_mean,
    const float* __restrict__ w_dg_x, const float* __restrict__ w_dg_h,
    const float* __restrict__ w_xz,  const float* __restrict__ w_hz,  const float* __restrict__ w_mz,
    const float* __restrict__ w_xr,  const float* __restrict__ w_hr,  const float* __restrict__ w_mr,
    const float* __restrict__ w_xh,  const float* __restrict__ w_hh,  const float* __restrict__ w_mh,
    const float* __restrict__ b_dg_x, const float* __restrict__ b_dg_h,
    const float* __restrict__ b_z,   const float* __restrict__ b_r,   const float* __restrict__ b_h,
    const float* __restrict__ w_hy,  const float* __restrict__ b_y,
    float* __restrict__ out)
{
    // sbuf[b][t][feat] = {gh, az, ar, ah}; +2 pad rows so the consumer can
    // prefetch unconditionally at distance 2 (pad reads land in dead regs).
    __shared__ float4 sbuf[2][CSTEPS + 2][32];   // 43 KB

    const int lane = threadIdx.x & 31;
    const int wid  = threadIdx.x >> 5;       // 0 = consumer, 1..3 = producers
    const int i    = blockIdx.x * 32 + lane; // feature index

    if (wid != 0) {
        // ------------------ PRODUCER ------------------
        const float xm  = x_mean[i];
        const float wdx = w_dg_x[i], wdh = w_dg_h[i];
        const float bdx = b_dg_x[i], bdh = b_dg_h[i];
        const float cz_x = 0.5f * w_xz[i], cz_m = 0.5f * w_mz[i], cz_b = 0.5f * b_z[i];
        const float cr_x = 0.5f * w_xr[i], cr_m = 0.5f * w_mr[i], cr_b = 0.5f * b_r[i];
        const float ch_x = w_xh[i],        ch_m = w_mh[i],        ch_b = b_h[i];

        const float4* __restrict__ X4 = reinterpret_cast<const float4*>(inp + (size_t)i * TLEN);
        const float4* __restrict__ M4 = reinterpret_cast<const float4*>(inp + (size_t)F * TLEN + (size_t)i * TLEN);
        const float4* __restrict__ D4 = reinterpret_cast<const float4*>(inp + (size_t)2 * F * TLEN + (size_t)i * TLEN);

        const int w = wid - 1; // 0..2  -> groups g = w, w+3, w+6 (+ w+9 for w==0)
        const int ng = (w == 0) ? 4 : 3;

        float4 xg[4], mg[4], dg[4];

        for (int c = 0; c < CHUNKS; ++c) {
            const int b = c & 1;

            // batch ALL global loads for this chunk first (max MLP, before the
            // empty-barrier wait: LDG doesn't touch SMEM so this is safe)
            #pragma unroll
            for (int j = 0; j < 4; ++j) {
                if (j < ng) {
                    const int f4idx = c * G4 + (w + 3 * j);
                    xg[j] = X4[f4idx];
                    mg[j] = M4[f4idx];
                    dg[j] = D4[f4idx];
                }
            }

            if (c >= 2) BAR_SYNC(3 + b);              // wait: consumer freed buffer b

            #pragma unroll
            for (int j = 0; j < 4; ++j) {
                if (j >= ng) break;
                const int g = w + 3 * j;
                const float xs[4] = {xg[j].x, xg[j].y, xg[j].z, xg[j].w};
                const float ms[4] = {mg[j].x, mg[j].y, mg[j].z, mg[j].w};
                const float ds[4] = {dg[j].x, dg[j].y, dg[j].z, dg[j].w};

                #pragma unroll
                for (int k = 0; k < 4; ++k) {
                    float x = xs[k], m = ms[k], d = ds[k];
                    float gx = __expf(-fmaxf(fmaf(wdx, d, bdx), 0.0f));
                    float gh = __expf(-fmaxf(fmaf(wdh, d, bdh), 0.0f));
                    float xi = fmaf(gx, x - xm, xm);       // decay-imputed
                    float xp = fmaf(m, x - xi, xi);        // mask blend
                    float az = fmaf(cz_x, xp, fmaf(cz_m, m, cz_b));
                    float ar = fmaf(cr_x, xp, fmaf(cr_m, m, cr_b));
                    float ah = fmaf(ch_x, xp, fmaf(ch_m, m, ch_b));
                    sbuf[b][g * 4 + k][lane] = make_float4(gh, az, ar, ah);
                }
            }
            asm volatile("membar.cta;" ::: "memory");     // STS visible before arrive
            BAR_ARRIVE(1 + b);                            // signal: buffer b full
        }
        return;
    }

    // ------------------ CONSUMER (warp 0) ------------------
    const float cz_h = 0.5f * w_hz[i];
    const float cr_h = 0.5f * w_hr[i];
    const float ch_h = 0.5f * w_hh[i];   // folds r = 0.5*s_r + 0.5

    float h = 0.0f;

    for (int c = 0; c < CHUNKS; ++c) {
        const int b = c & 1;
        BAR_SYNC(1 + b);                                  // wait: buffer b full

        // distance-2 software pipeline; loads are UNCONDITIONAL (padded rows)
        float4 p0 = sbuf[b][0][lane];
        float4 p1 = sbuf[b][1][lane];

        #pragma unroll 4
        for (int t = 0; t < CSTEPS; ++t) {
            float4 p2 = sbuf[b][t + 2][lane];             // prefetch, 2 steps ahead

            const float gh = p0.x, az = p0.y, ar = p0.z, ah = p0.w;
            float Az = cz_h * gh;                         // off-chain
            float Ar = cr_h * gh;
            float Ph = ch_h * gh;
            float hg = gh * h;
            float q  = Ph * h;
            float qa = q + ah;
            float sz = fast_tanh(fmaf(Az, h, az));        // z-path (24 cyc, off-chain)
            float z  = fmaf(sz, 0.5f, 0.5f);
            float w0 = fmaf(-z, hg, hg);                  // (1-z)*hg
            float sr = fast_tanh(fmaf(Ar, h, ar));        // chain
            float ht = fast_tanh(fmaf(q, sr, qa));        // chain
            h = fmaf(z, ht, w0);                          // chain

            p0 = p1; p1 = p2;
        }

        if (c < CHUNKS - 2) BAR_ARRIVE(3 + b);            // free buffer b
    }

    // fused output head: per-warp partial dot, then last-CTA-out final reduce
    float a0 = w_hy[i] * h;
    float a1 = w_hy[F + i] * h;
    #pragma unroll
    for (int o = 16; o > 0; o >>= 1) {
        a0 += __shfl_down_sync(0xffffffffu, a0, o);
        a1 += __shfl_down_sync(0xffffffffu, a1, o);
    }

    bool last = false;
    if (lane == 0) {
        g_part0[blockIdx.x] = a0;
        g_part1[blockIdx.x] = a1;
        __threadfence();
        unsigned old = atomicAdd(&g_count, 1u);
        last = (old == NWARP - 1);
    }
    last = __shfl_sync(0xffffffffu, last ? 1 : 0, 0) != 0;

    if (last) {
        __threadfence();
        float s0 = 0.0f, s1 = 0.0f;
        #pragma unroll
        for (int k = lane; k < NWARP; k += 32) {
            s0 += g_part0[k];
            s1 += g_part1[k];
        }
        #pragma unroll
        for (int o = 16; o > 0; o >>= 1) {
            s0 += __shfl_down_sync(0xffffffffu, s0, o);
            s1 += __shfl_down_sync(0xffffffffu, s1, o);
        }
        if (lane == 0) {
            out[0] = s0 + b_y[0];
            out[1] = s1 + b_y[1];
            g_count = 0;                                  // reset for next replay
        }
    }
}

extern "C" void kernel_launch(void* const* d_in, const int* in_sizes, int n_in,
                              void* d_out, int out_size)
{
    const float* inp    = (const float*)d_in[0];
    const float* x_mean = (const float*)d_in[1];
    const float* w_dg_x = (const float*)d_in[2];
    const float* w_dg_h = (const float*)d_in[3];
    const float* w_xz   = (const float*)d_in[4];
    const float* w_hz   = (const float*)d_in[5];
    const float* w_mz   = (const float*)d_in[6];
    const float* w_xr   = (const float*)d_in[7];
    const float* w_hr   = (const float*)d_in[8];
    const float* w_mr   = (const float*)d_in[9];
    const float* w_xh   = (const float*)d_in[10];
    const float* w_hh   = (const float*)d_in[11];
    const float* w_mh   = (const float*)d_in[12];
    const float* w_hy   = (const float*)d_in[13];
    const float* b_dg_x = (const float*)d_in[14];
    const float* b_dg_h = (const float*)d_in[15];
    const float* b_z    = (const float*)d_in[16];
    const float* b_r    = (const float*)d_in[17];
    const float* b_h    = (const float*)d_in[18];
    const float* b_y    = (const float*)d_in[19];
    float* out = (float*)d_out;

    grud_scan_kernel<<<NWARP, 128>>>(
        inp, x_mean, w_dg_x, w_dg_h,
        w_xz, w_hz, w_mz, w_xr, w_hr, w_mr, w_xh, w_hh, w_mh,
        b_dg_x, b_dg_h, b_z, b_r, b_h, w_hy, b_y, out);
}

// round 5
// speedup vs baseline: 2.8893x; 1.0395x over previous
#include <cuda_runtime.h>
#include <cuda_bf16.h>

#define F 4096
#define TLEN 2000
#define NWARP (F / 32)         // 128 CTAs, one consumer warp each
#define CSTEPS 40              // steps per chunk
#define ROWS (CSTEPS + 2)      // +2 pad rows for unconditional dist-2 prefetch
#define G4 (CSTEPS / 4)        // float4 groups per chunk = 10
#define CHUNKS (TLEN / CSTEPS) // 50
// dynamic smem: two SoA ring buffers, each [2][ROWS][32] float4
#define BUF_F4 (2 * ROWS * 32)
#define SMEM_BYTES (2 * BUF_F4 * 16)

// cross-CTA reduction scratch
__device__ float g_part0[NWARP];
__device__ float g_part1[NWARP];
__device__ unsigned g_count = 0;

__device__ __forceinline__ float fast_tanh(float x) {
    float y;
    asm("tanh.approx.f32 %0, %1;" : "=f"(y) : "f"(x));
    return y;
}

#define BAR_SYNC(id)   asm volatile("bar.sync %0, 128;"   :: "r"(id) : "memory")
#define BAR_ARRIVE(id) asm volatile("bar.arrive %0, 128;" :: "r"(id) : "memory")
// barrier ids: FULL buffer b -> 1+b ; EMPTY buffer b -> 3+b

__global__ void __launch_bounds__(128, 1) grud_scan_kernel(
    const float* __restrict__ inp,
    const float* __restrict__ x_mean,
    const float* __restrict__ w_dg_x, const float* __restrict__ w_dg_h,
    const float* __restrict__ w_xz,  const float* __restrict__ w_hz,  const float* __restrict__ w_mz,
    const float* __restrict__ w_xr,  const float* __restrict__ w_hr,  const float* __restrict__ w_mr,
    const float* __restrict__ w_xh,  const float* __restrict__ w_hh,  const float* __restrict__ w_mh,
    const float* __restrict__ b_dg_x, const float* __restrict__ b_dg_h,
    const float* __restrict__ b_z,   const float* __restrict__ b_r,   const float* __restrict__ b_h,
    const float* __restrict__ w_hy,  const float* __restrict__ b_y,
    float* __restrict__ out)
{
    extern __shared__ float4 smem4[];
    float4* __restrict__ bufA = smem4;            // {Ar, ar, Ph, ah}
    float4* __restrict__ bufB = smem4 + BUF_F4;   // {Az, az, gh, -}

    const int lane = threadIdx.x & 31;
    const int wid  = threadIdx.x >> 5;       // 0 = consumer, 1..3 = producers
    const int i    = blockIdx.x * 32 + lane; // feature index

    if (wid != 0) {
        // ------------------ PRODUCER ------------------
        const float xm  = x_mean[i];
        const float wdx = w_dg_x[i], wdh = w_dg_h[i];
        const float bdx = b_dg_x[i], bdh = b_dg_h[i];
        const float cz_h = 0.5f * w_hz[i];
        const float cr_h = 0.5f * w_hr[i];
        const float ch_h = 0.5f * w_hh[i];   // folds r = 0.5*s_r + 0.5
        const float cz_x = 0.5f * w_xz[i], cz_m = 0.5f * w_mz[i], cz_b = 0.5f * b_z[i];
        const float cr_x = 0.5f * w_xr[i], cr_m = 0.5f * w_mr[i], cr_b = 0.5f * b_r[i];
        const float ch_x = w_xh[i],        ch_m = w_mh[i],        ch_b = b_h[i];

        const float4* __restrict__ X4 = reinterpret_cast<const float4*>(inp + (size_t)i * TLEN);
        const float4* __restrict__ M4 = reinterpret_cast<const float4*>(inp + (size_t)F * TLEN + (size_t)i * TLEN);
        const float4* __restrict__ D4 = reinterpret_cast<const float4*>(inp + (size_t)2 * F * TLEN + (size_t)i * TLEN);

        const int w = wid - 1;              // 0..2 -> groups g = w, w+3, w+6 (+ w+9 for w==0)
        const int ng = (w == 0) ? 4 : 3;

        float4 xg[4], mg[4], dg[4];

        for (int c = 0; c < CHUNKS; ++c) {
            const int b = c & 1;

            // batch ALL global loads for this chunk first (max MLP), before the
            // empty-barrier wait (LDG doesn't touch SMEM, so this is safe)
            #pragma unroll
            for (int j = 0; j < 4; ++j) {
                if (j < ng) {
                    const int f4idx = c * G4 + (w + 3 * j);
                    xg[j] = X4[f4idx];
                    mg[j] = M4[f4idx];
                    dg[j] = D4[f4idx];
                }
            }

            if (c >= 2) BAR_SYNC(3 + b);    // wait: consumer freed buffer b

            #pragma unroll
            for (int j = 0; j < 4; ++j) {
                if (j >= ng) break;
                const int g = w + 3 * j;
                const float xs[4] = {xg[j].x, xg[j].y, xg[j].z, xg[j].w};
                const float ms[4] = {mg[j].x, mg[j].y, mg[j].z, mg[j].w};
                const float ds[4] = {dg[j].x, dg[j].y, dg[j].z, dg[j].w};

                #pragma unroll
                for (int k = 0; k < 4; ++k) {
                    float x = xs[k], m = ms[k], d = ds[k];
                    float gx = __expf(-fmaxf(fmaf(wdx, d, bdx), 0.0f));
                    float gh = __expf(-fmaxf(fmaf(wdh, d, bdh), 0.0f));
                    float xi = fmaf(gx, x - xm, xm);       // decay-imputed
                    float xp = fmaf(m, x - xi, xi);        // mask blend
                    float az = fmaf(cz_x, xp, fmaf(cz_m, m, cz_b));
                    float ar = fmaf(cr_x, xp, fmaf(cr_m, m, cr_b));
                    float ah = fmaf(ch_x, xp, fmaf(ch_m, m, ch_b));
                    float Az = cz_h * gh;
                    float Ar = cr_h * gh;
                    float Ph = ch_h * gh;
                    const int row = (b * ROWS + g * 4 + k) * 32 + lane;
                    bufA[row] = make_float4(Ar, ar, Ph, ah);
                    bufB[row] = make_float4(Az, az, gh, 0.0f);
                }
            }
            asm volatile("membar.cta;" ::: "memory");     // STS visible before arrive
            BAR_ARRIVE(1 + b);                            // signal: buffer b full
        }
        return;
    }

    // ------------------ CONSUMER (warp 0) ------------------
    // lookahead state: h_t is never materialized on the chain; instead we carry
    // (ht_prev, z_prev, w0_prev) with h_t = z_prev*ht_prev + w0_prev.
    float htp = 0.0f, zp = 0.0f, w0p = 0.0f;   // => h_0 = 0

    for (int c = 0; c < CHUNKS; ++c) {
        const int b = c & 1;
        BAR_SYNC(1 + b);                        // wait: buffer b full

        const int base = b * ROWS * 32 + lane;
        float4 a0v = bufA[base], a1v = bufA[base + 32];
        float4 b0v = bufB[base], b1v = bufB[base + 32];

        #pragma unroll 8
        for (int t = 0; t < CSTEPS; ++t) {
            float4 a2v = bufA[base + (t + 2) * 32];   // unconditional dist-2 prefetch
            float4 b2v = bufB[base + (t + 2) * 32];

            const float Ar = a0v.x, ar = a0v.y, Ph = a0v.z, ah = a0v.w;
            const float Az = b0v.x, az = b0v.y, gh = b0v.z;

            // coefficients of (linear in htp) quantities — all off-chain
            float c1 = Ar * zp;
            float c0 = fmaf(Ar, w0p, ar);
            float argr = fmaf(c1, htp, c0);           // CHAIN +4
            float d1 = Ph * zp;
            float d0 = Ph * w0p;
            float e0 = d0 + ah;
            float q  = fmaf(d1, htp, d0);             // ready +8 (off-chain)
            float qa = fmaf(d1, htp, e0);
            float h  = fmaf(zp, htp, w0p);            // h_t, off-chain
            float sr = fast_tanh(argr);               // CHAIN +20
            float sz = fast_tanh(fmaf(Az, h, az));    // z-path, off-chain
            float z  = fmaf(sz, 0.5f, 0.5f);
            float hg = gh * h;
            float w0 = fmaf(-z, hg, hg);              // (1-z)*hg
            float argh = fmaf(q, sr, qa);             // CHAIN +24
            float ht = fast_tanh(argh);               // CHAIN +40

            zp = z; w0p = w0; htp = ht;
            a0v = a1v; a1v = a2v;
            b0v = b1v; b1v = b2v;
        }

        if (c < CHUNKS - 2) BAR_ARRIVE(3 + b);    // free buffer b
    }

    const float h = fmaf(zp, htp, w0p);           // materialize final h

    // fused output head: per-warp partial dot, then last-CTA-out final reduce
    float a0 = w_hy[i] * h;
    float a1 = w_hy[F + i] * h;
    #pragma unroll
    for (int o = 16; o > 0; o >>= 1) {
        a0 += __shfl_down_sync(0xffffffffu, a0, o);
        a1 += __shfl_down_sync(0xffffffffu, a1, o);
    }

    bool last = false;
    if (lane == 0) {
        g_part0[blockIdx.x] = a0;
        g_part1[blockIdx.x] = a1;
        __threadfence();
        unsigned old = atomicAdd(&g_count, 1u);
        last = (old == NWARP - 1);
    }
    last = __shfl_sync(0xffffffffu, last ? 1 : 0, 0) != 0;

    if (last) {
        __threadfence();
        float s0 = 0.0f, s1 = 0.0f;
        #pragma unroll
        for (int k = lane; k < NWARP; k += 32) {
            s0 += g_part0[k];
            s1 += g_part1[k];
        }
        #pragma unroll
        for (int o = 16; o > 0; o >>= 1) {
            s0 += __shfl_down_sync(0xffffffffu, s0, o);
            s1 += __shfl_down_sync(0xffffffffu, s1, o);
        }
        if (lane == 0) {
            out[0] = s0 + b_y[0];
            out[1] = s1 + b_y[1];
            g_count = 0;                          // reset for next replay
        }
    }
}

extern "C" void kernel_launch(void* const* d_in, const int* in_sizes, int n_in,
                              void* d_out, int out_size)
{
    const float* inp    = (const float*)d_in[0];
    const float* x_mean = (const float*)d_in[1];
    const float* w_dg_x = (const float*)d_in[2];
    const float* w_dg_h = (const float*)d_in[3];
    const float* w_xz   = (const float*)d_in[4];
    const float* w_hz   = (const float*)d_in[5];
    const float* w_mz   = (const float*)d_in[6];
    const float* w_xr   = (const float*)d_in[7];
    const float* w_hr   = (const float*)d_in[8];
    const float* w_mr   = (const float*)d_in[9];
    const float* w_xh   = (const float*)d_in[10];
    const float* w_hh   = (const float*)d_in[11];
    const float* w_mh   = (const float*)d_in[12];
    const float* w_hy   = (const float*)d_in[13];
    const float* b_dg_x = (const float*)d_in[14];
    const float* b_dg_h = (const float*)d_in[15];
    const float* b_z    = (const float*)d_in[16];
    const float* b_r    = (const float*)d_in[17];
    const float* b_h    = (const float*)d_in[18];
    const float* b_y    = (const float*)d_in[19];
    float* out = (float*)d_out;

    static int smem_set = 0;
    if (!smem_set) {
        cudaFuncSetAttribute(grud_scan_kernel,
                             cudaFuncAttributeMaxDynamicSharedMemorySize, SMEM_BYTES);
        smem_set = 1;
    }

    grud_scan_kernel<<<NWARP, 128, SMEM_BYTES>>>(
        inp, x_mean, w_dg_x, w_dg_h,
        w_xz, w_hz, w_mz, w_xr, w_hr, w_mr, w_xh, w_hh, w_mh,
        b_dg_x, b_dg_h, b_z, b_r, b_h, w_hy, b_y, out);
}